// round 13
// baseline (speedup 1.0000x reference)
#include <cuda_runtime.h>
#include <math.h>

#define BB 2
#define LL 1024
#define DD 1024
#define NN 16
#define RR 64
#define PBM 8    // producer rows per block -> grid 256
#define TG 32    // 32 t-groups of 32 steps

// scratch (no device allocations allowed)
__device__ float g_delta[BB * LL * DD];
__device__ float g_Bt[BB * LL * NN];
__device__ float g_Ct[BB * LL * NN];
__device__ int   g_cnt[TG];
__device__ int   g_flag[TG];

__device__ __forceinline__ int ld_acquire(const int* p) {
    int v;
    asm volatile("ld.global.acquire.gpu.b32 %0, [%1];" : "=r"(v) : "l"(p) : "memory");
    return v;
}

__global__ void reset_k() {
    int i = threadIdx.x;
    if (i < TG) { g_cnt[i] = 0; g_flag[i] = 0; }
}

// ---------------------------------------------------------------------------
// Producer (R12 verbatim numerics) + readiness publish.
// Block i covers rows m0..m0+7 (one batch half, one t-octet); 8 blocks
// complete a 32-step t-group across both batch halves.
// ---------------------------------------------------------------------------
__global__ void __launch_bounds__(256) producer_k(
    const float* __restrict__ x,   // [2048, 1024]
    const float* __restrict__ W1,  // [1024, 64]
    const float* __restrict__ WB,  // [1024, 16]
    const float* __restrict__ WC,  // [1024, 16]
    const float* __restrict__ W2)  // [64, 1024]
{
    __shared__ float As[PBM][64];
    __shared__ float Ws[64][96];
    __shared__ float Ts[PBM][64];

    int tid = threadIdx.x;
    int m0 = blockIdx.x * PBM;

    int tc = tid & 31;
    int tr = tid >> 5;

    float a0 = 0.f, a1 = 0.f, a2 = 0.f;

    for (int k0 = 0; k0 < 1024; k0 += 64) {
        __syncthreads();
        if (tid < 128) {
            int r = tid >> 4, c = (tid & 15) * 4;
            *(float4*)&As[r][c] = *(const float4*)&x[(size_t)(m0 + r) * 1024 + k0 + c];
        }
#pragma unroll
        for (int j = 0; j < 4; ++j) {
            int idx = (tid + j * 256) * 4;
            int r = idx >> 6, c = idx & 63;
            *(float4*)&Ws[r][c] = *(const float4*)&W1[(size_t)(k0 + r) * 64 + c];
        }
        {
            int r = tid >> 2, c = (tid & 3) * 4;
            *(float4*)&Ws[r][64 + c] = *(const float4*)&WB[(size_t)(k0 + r) * 16 + c];
            *(float4*)&Ws[r][80 + c] = *(const float4*)&WC[(size_t)(k0 + r) * 16 + c];
        }
        __syncthreads();

#pragma unroll
        for (int k = 0; k < 64; ++k) {
            float a = As[tr][k];
            a0 = fmaf(a, Ws[k][tc],      a0);
            a1 = fmaf(a, Ws[k][tc + 32], a1);
            a2 = fmaf(a, Ws[k][tc + 64], a2);
        }
    }

    if (tc < 16) {
        g_Bt[(size_t)(m0 + tr) * 16 + tc] = a2;
    } else {
        g_Ct[(size_t)(m0 + tr) * 16 + (tc - 16)] = a2;
    }
    __syncthreads();
    Ts[tr][tc]      = a0;
    Ts[tr][tc + 32] = a1;
    __syncthreads();

    int c0 = tid * 4;
    float4 acc[PBM];
#pragma unroll
    for (int r = 0; r < PBM; ++r) { acc[r].x = 0.f; acc[r].y = 0.f; acc[r].z = 0.f; acc[r].w = 0.f; }

#pragma unroll 4
    for (int k = 0; k < 64; ++k) {
        float4 w = *(const float4*)&W2[(size_t)k * 1024 + c0];
#pragma unroll
        for (int r = 0; r < PBM; ++r) {
            float t = Ts[r][k];
            acc[r].x = fmaf(t, w.x, acc[r].x);
            acc[r].y = fmaf(t, w.y, acc[r].y);
            acc[r].z = fmaf(t, w.z, acc[r].z);
            acc[r].w = fmaf(t, w.w, acc[r].w);
        }
    }

#pragma unroll
    for (int r = 0; r < PBM; ++r) {
        float4 v;
        v.x = fmaxf(acc[r].x, 0.f) + log1pf(expf(-fabsf(acc[r].x)));
        v.y = fmaxf(acc[r].y, 0.f) + log1pf(expf(-fabsf(acc[r].y)));
        v.z = fmaxf(acc[r].z, 0.f) + log1pf(expf(-fabsf(acc[r].z)));
        v.w = fmaxf(acc[r].w, 0.f) + log1pf(expf(-fabsf(acc[r].w)));
        *(float4*)&g_delta[(size_t)(m0 + r) * 1024 + c0] = v;
    }

    // publish: this block's 8 rows done -> count toward its t-group
    __threadfence();
    __syncthreads();
    if (tid == 0) {
        int g = (m0 & 1023) >> 5;
        if (atomicAdd(&g_cnt[g], 1) == 7)
            atomicExch(&g_flag[g], 1);
    }
}

// ---------------- sequential resonance scan (R5 FP sequence + group gates) --
__global__ void __launch_bounds__(256, 1) scan_k(
    const float* __restrict__ x, const float* __restrict__ A_log,
    const float* __restrict__ Dskip, float* __restrict__ y)
{
    int tid = threadIdx.x;
    int bid = blockIdx.x;                 // 0..127
    int b = bid >> 6;                     // 0..1
    int d = ((bid & 63) << 4) | (tid >> 4);
    int n = tid & 15;

    float An = expf(A_log[n]);
    float phi = (float)n * 0.39269908169872414f;
    float sphi, cphi;
    sincosf(phi, &sphi, &cphi);
    float hx = __fmul_rn(0.01f, cphi), hy = __fmul_rn(0.01f, sphi);
    float dsk = Dskip[d];

    size_t rowbase = ((size_t)b * LL) * DD + d;
    const float* xp = x + rowbase;
    const float* dp = g_delta + rowbase;
    const float* bp = g_Bt + ((size_t)b * LL) * NN + n;
    const float* cp = g_Ct + ((size_t)b * LL) * NN + n;
    float* yp = y + rowbase;

    // wait for t-group 0 (rows 0..31, both batch halves)
    while (ld_acquire(&g_flag[0]) == 0) { __nanosleep(100); }

    float xv = __ldg(xp);
    float dv = __ldg(dp);
    float bn = __ldg(bp);
    float cn = __ldg(cp);

#pragma unroll 2
    for (int t = 0; t < LL; ++t) {
        int tnext = t + 1;
        if ((tnext & 31) == 0 && tnext < LL) {
            const int* fp = &g_flag[tnext >> 5];
            while (ld_acquire(fp) == 0) { __nanosleep(100); }
        }

        int tn = (t < LL - 1) ? (t + 1) : t;
        float xv2 = __ldg(xp + (size_t)tn * DD);
        float dv2 = __ldg(dp + (size_t)tn * DD);
        float bn2 = __ldg(bp + tn * NN);
        float cn2 = __ldg(cp + tn * NN);

        // ---- fractal_compress(h, e) ----
        float mag = __fsqrt_rn(__fadd_rn(__fadd_rn(__fmul_rn(hx, hx), __fmul_rn(hy, hy)), 1e-8f));
        float ph  = atan2f(hy, __fadd_rn(hx, 1e-10f));
        float e   = __fadd_rn(1.0f, __fmul_rn(dv, An));
        float cm  = fminf(expf(__fmul_rn(e, logf(__fadd_rn(mag, 1e-8f)))), 10.0f);
        float sph, cph;
        sincosf(ph, &sph, &cph);
        float hcx = __fmul_rn(cm, cph);
        float hcy = __fmul_rn(cm, sph);

        // ---- injection on carrier phases ----
        float u   = __fmul_rn(xv, bn);
        float ijx = __fmul_rn(u, cphi);
        float ijy = __fmul_rn(u, sphi);

        // ---- resonance gate: gamma = 0.5 * cos((pa-pb)/2)^2 ----
        float pa = atan2f(ijy, __fadd_rn(ijx, 1e-10f));
        float pb = atan2f(hcy, __fadd_rn(hcx, 1e-10f));
        float cd = cosf(__fmul_rn(__fsub_rn(pa, pb), 0.5f));
        float gam = __fmul_rn(0.5f, __fmul_rn(cd, cd));

        // ---- inject + mag_squash ----
        float sx = __fadd_rn(hcx, __fmul_rn(gam, ijx));
        float sy = __fadd_rn(hcy, __fmul_rn(gam, ijy));
        float sm = __fsqrt_rn(__fadd_rn(__fadd_rn(__fmul_rn(sx, sx), __fmul_rn(sy, sy)), 1e-8f));
        float ps = atan2f(sy, __fadd_rn(sx, 1e-10f));
        float th = tanhf(sm);
        float sps, cps;
        sincosf(ps, &sps, &cps);
        hx = __fmul_rn(th, cps);
        hy = __fmul_rn(th, sps);

        // ---- readout ----
        float v = __fmul_rn(hx, cn);
        v += __shfl_xor_sync(0xffffffffu, v, 8);
        v += __shfl_xor_sync(0xffffffffu, v, 4);
        v += __shfl_xor_sync(0xffffffffu, v, 2);
        v += __shfl_xor_sync(0xffffffffu, v, 1);
        if (n == 0) yp[(size_t)t * DD] = __fadd_rn(__fmul_rn(xv, dsk), v);

        xv = xv2; dv = dv2; bn = bn2; cn = cn2;
    }
}

extern "C" void kernel_launch(void* const* d_in, const int* in_sizes, int n_in,
                              void* d_out, int out_size)
{
    const float *x = 0, *A_log = 0, *W_dt1 = 0, *W_dt2 = 0, *W_B = 0, *W_C = 0, *Dskip = 0;
    for (int i = 0; i < n_in; ++i) {
        const float* p = (const float*)d_in[i];
        int s = in_sizes[i];
        if (s == BB * LL * DD)      { if (!x) x = p; }
        else if (s == NN)           { if (!A_log) A_log = p; }
        else if (s == DD * RR)      { if (!W_dt1) W_dt1 = p; else W_dt2 = p; }
        else if (s == DD * NN)      { if (!W_B) W_B = p; else W_C = p; }
        else if (s == DD)           { if (!Dskip) Dskip = p; }
    }
    float* y = (float*)d_out;

    // flags reset on the main stream (ordered before both branches)
    reset_k<<<1, 32>>>();

    // fork a side stream inside capture via event edges (no allocations)
    cudaStream_t s1;
    cudaStreamCreateWithFlags(&s1, cudaStreamNonBlocking);
    cudaEvent_t ef, ej;
    cudaEventCreateWithFlags(&ef, cudaEventDisableTiming);
    cudaEventCreateWithFlags(&ej, cudaEventDisableTiming);

    cudaEventRecord(ef, 0);
    cudaStreamWaitEvent(s1, ef, 0);

    // producer runs concurrently with the gated scan
    producer_k<<<BB * LL / PBM, 256, 0, s1>>>(x, W_dt1, W_B, W_C, W_dt2);
    cudaEventRecord(ej, s1);

    scan_k<<<128, 256>>>(x, A_log, Dskip, y);

    // join: main stream completes only after the producer branch
    cudaStreamWaitEvent(0, ej, 0);
}